// round 6
// baseline (speedup 1.0000x reference)
#include <cuda_runtime.h>
#include <cstdint>

// AttentionLayer: B=2048, N=64, D=256, H=16
//   m_i[h]  = sum_d members[b,i,d]*item[b,d]*W1[d,h]
//   s[h]    = sum_i m_i[h] ; pre = 64*m_i - s + b1 ; relu ; logit = relu@W2 + b2
//   out[b,i] = softmax_i(logit)
//
// R6: block = 64 threads = 2 warps = 1 batch, 2 batches per block (grid 1024,
// single wave). Warp p covers heads 8p..8p+7; lane owns 4 heads
// (hgrp = lane&1 -> h0 = 8p+4*hgrp) x 16 d (quads 16t + (lane>>1)).
// LDS wavefronts halved vs R5. Private per-warp cp.async ring -> NO block
// barriers in the main loop; warps fully decoupled.

constexpr int Bb = 2048;
constexpr int Nn = 64;
constexpr int Dd = 256;
constexpr int Hh = 16;
constexpr int THREADS = 64;
constexpr int RING = 4;                // slots of 2 rows (2 KB) per warp
constexpr int MSTR = 18;               // mS row stride: 72B rows, 8B-aligned

#define FMA2(acc, a, w)  asm("fma.rn.f32x2 %0, %1, %2, %0;" : "+l"(acc) : "l"(a), "l"(w))
#define ADD2(d, a, b_)   asm("add.rn.f32x2 %0, %1, %2;" : "=l"(d) : "l"(a), "l"(b_))
#define PACK2(d, lo, hi) asm("mov.b64 %0, {%1, %2};" : "=l"(d) : "f"(lo), "f"(hi))
#define UNPACK2(lo, hi, v) asm("mov.b64 {%0, %1}, %2;" : "=f"(lo), "=f"(hi) : "l"(v))

__device__ __forceinline__ uint32_t smem_u32(const void* p) {
    uint32_t a;
    asm("{ .reg .u64 t; cvta.to.shared.u64 t, %1; cvt.u32.u64 %0, t; }"
        : "=r"(a) : "l"(p));
    return a;
}
__device__ __forceinline__ void cp_async16(uint32_t dst, const void* src) {
    asm volatile("cp.async.cg.shared.global [%0], [%1], 16;" :: "r"(dst), "l"(src));
}
__device__ __forceinline__ void cp_commit() {
    asm volatile("cp.async.commit_group;" ::: "memory");
}
__device__ __forceinline__ void cp_wait2() {
    asm volatile("cp.async.wait_group %0;" :: "n"(RING - 2) : "memory");
}

__global__ __launch_bounds__(THREADS, 8)
void attn_kernel(const float* __restrict__ members,
                 const float* __restrict__ item,
                 const float* __restrict__ W1,
                 const float* __restrict__ b1,
                 const float* __restrict__ W2,
                 const float* __restrict__ b2,
                 float* __restrict__ out)
{
    __shared__ float4 ring[2][RING][2][Dd / 4];   // [warp][slot][row] = 16 KB
    __shared__ float  mS[Nn * MSTR];              // 4.6 KB
    __shared__ float  sS[Hh];
    __shared__ float  red[2][2];                  // [max|sum][warp]

    const int tid  = threadIdx.x;
    const int p    = tid >> 5;                 // warp: heads 8p..8p+7
    const int lane = tid & 31;
    const int hgrp = lane & 1;                 // 0: heads 8p..+3, 1: 8p+4..+7
    const int ds   = lane >> 1;                // d-sixteenth: quads 16t + ds
    const int h0   = 8 * p + 4 * hgrp;
    const uint32_t ringBase = smem_u32(&ring[p][0][0][0]);

    for (int bat = 0; bat < 2; bat++) {
        const int b = blockIdx.x + bat * (Bb / 2);
        const float4* grow = (const float4*)(members + (size_t)b * Nn * Dd);

        // ---- prologue: slots 0..2 (rows 0..5) in flight (private ring) ----
        #pragma unroll
        for (int it = 0; it < RING - 1; it++) {
            const uint32_t d0 = ringBase + it * 2048 + lane * 16;
            const float4* g = grow + 2 * it * 64;
            cp_async16(d0,        g + lane);
            cp_async16(d0 + 512,  g + lane + 32);
            cp_async16(d0 + 1024, g + 64 + lane);
            cp_async16(d0 + 1536, g + 64 + lane + 32);
            cp_commit();
        }

        // ---- register weights: lane's 4 heads x 16 d ----
        // wreg[8t + 0..3] = (W1[d,h0+j]*it[d], W1[d+1,h0+j]*it[d+1]) for quad 16t+ds
        // wreg[8t + 4..7] = same for (d+2, d+3)
        const float* itG = item + (size_t)b * Dd;
        unsigned long long wreg[32];
        #pragma unroll
        for (int t = 0; t < 4; t++) {
            const int d0 = (16 * t + ds) * 4;
            const float4 it4 = __ldg((const float4*)&itG[d0]);
            const float4 wa = __ldg((const float4*)&W1[(d0 + 0) * Hh + h0]);
            const float4 wb = __ldg((const float4*)&W1[(d0 + 1) * Hh + h0]);
            const float4 wc = __ldg((const float4*)&W1[(d0 + 2) * Hh + h0]);
            const float4 wd = __ldg((const float4*)&W1[(d0 + 3) * Hh + h0]);
            PACK2(wreg[8 * t + 0], wa.x * it4.x, wb.x * it4.y);
            PACK2(wreg[8 * t + 1], wa.y * it4.x, wb.y * it4.y);
            PACK2(wreg[8 * t + 2], wa.z * it4.x, wb.z * it4.y);
            PACK2(wreg[8 * t + 3], wa.w * it4.x, wb.w * it4.y);
            PACK2(wreg[8 * t + 4], wc.x * it4.z, wd.x * it4.w);
            PACK2(wreg[8 * t + 5], wc.y * it4.z, wd.y * it4.w);
            PACK2(wreg[8 * t + 6], wc.z * it4.z, wd.z * it4.w);
            PACK2(wreg[8 * t + 7], wc.w * it4.z, wd.w * it4.w);
        }

        // ---- main loop: 32 iterations x 2 rows, no block barriers ----
        unsigned long long sAcc0 = 0ull, sAcc1 = 0ull;   // (s_h0,s_h1),(s_h2,s_h3)
        for (int i = 0; i < Nn / 2; i++) {
            cp_wait2();             // slot i landed (per-thread groups)
            __syncwarp();           // cross-lane visibility within this warp

            if (i + RING - 1 < Nn / 2) {   // refill slot i+3 (buffer (i-1)&3)
                const int it = i + RING - 1;
                const uint32_t d0 = ringBase + (it & (RING - 1)) * 2048 + lane * 16;
                const float4* g = grow + 2 * it * 64;
                cp_async16(d0,        g + lane);
                cp_async16(d0 + 512,  g + lane + 32);
                cp_async16(d0 + 1024, g + 64 + lane);
                cp_async16(d0 + 1536, g + 64 + lane + 32);
            }
            cp_commit();            // unconditional: wait arithmetic stays exact

            const ulonglong2* rA = (const ulonglong2*)&ring[p][i & (RING - 1)][0][0];
            const ulonglong2* rB = rA + 64;

            unsigned long long aA[4] = {0,0,0,0}, aB[4] = {0,0,0,0};
            #pragma unroll
            for (int t = 0; t < 4; t++) {
                const ulonglong2 va = rA[16 * t + ds];  // 16 addrs, 2-way bcast
                const ulonglong2 vb = rB[16 * t + ds];
                FMA2(aA[0], va.x, wreg[8 * t + 0]);
                FMA2(aA[1], va.x, wreg[8 * t + 1]);
                FMA2(aA[2], va.x, wreg[8 * t + 2]);
                FMA2(aA[3], va.x, wreg[8 * t + 3]);
                FMA2(aB[0], vb.x, wreg[8 * t + 0]);
                FMA2(aB[1], vb.x, wreg[8 * t + 1]);
                FMA2(aB[2], vb.x, wreg[8 * t + 2]);
                FMA2(aB[3], vb.x, wreg[8 * t + 3]);
                FMA2(aA[0], va.y, wreg[8 * t + 4]);
                FMA2(aA[1], va.y, wreg[8 * t + 5]);
                FMA2(aA[2], va.y, wreg[8 * t + 6]);
                FMA2(aA[3], va.y, wreg[8 * t + 7]);
                FMA2(aB[0], vb.y, wreg[8 * t + 4]);
                FMA2(aB[1], vb.y, wreg[8 * t + 5]);
                FMA2(aB[2], vb.y, wreg[8 * t + 6]);
                FMA2(aB[3], vb.y, wreg[8 * t + 7]);
            }
            // per-head horizontal add, pack (h0,h1) and (h2,h3)
            float x, y, m0, m1, m2, m3, n0, n1, n2, n3;
            UNPACK2(x, y, aA[0]); m0 = x + y;
            UNPACK2(x, y, aA[1]); m1 = x + y;
            UNPACK2(x, y, aA[2]); m2 = x + y;
            UNPACK2(x, y, aA[3]); m3 = x + y;
            UNPACK2(x, y, aB[0]); n0 = x + y;
            UNPACK2(x, y, aB[1]); n1 = x + y;
            UNPACK2(x, y, aB[2]); n2 = x + y;
            UNPACK2(x, y, aB[3]); n3 = x + y;
            unsigned long long mmA0, mmA1, mmB0, mmB1, tmp;
            PACK2(mmA0, m0, m1);  PACK2(mmA1, m2, m3);
            PACK2(mmB0, n0, n1);  PACK2(mmB1, n2, n3);
            // butterfly over the 16 d-split lanes (xor 2,4,8,16); 4 chains
            #pragma unroll
            for (int o = 2; o <= 16; o <<= 1) {
                tmp = __shfl_xor_sync(0xffffffffu, mmA0, o); ADD2(mmA0, mmA0, tmp);
                tmp = __shfl_xor_sync(0xffffffffu, mmA1, o); ADD2(mmA1, mmA1, tmp);
                tmp = __shfl_xor_sync(0xffffffffu, mmB0, o); ADD2(mmB0, mmB0, tmp);
                tmp = __shfl_xor_sync(0xffffffffu, mmB1, o); ADD2(mmB1, mmB1, tmp);
            }
            ADD2(sAcc0, sAcc0, mmA0);  ADD2(sAcc0, sAcc0, mmB0);
            ADD2(sAcc1, sAcc1, mmA1);  ADD2(sAcc1, sAcc1, mmB1);
            // publish: lane0/1 -> row 2i (h0..h3 / h4..h7), lane2/3 -> row 2i+1
            if (lane < 4) {
                const int r = 2 * i + (lane >> 1);
                unsigned long long* dst = (unsigned long long*)&mS[r * MSTR + h0];
                dst[0] = (lane & 2) ? mmB0 : mmA0;
                dst[1] = (lane & 2) ? mmB1 : mmA1;
            }
        }

        if (lane < 2) {
            unsigned long long* dst = (unsigned long long*)&sS[h0];
            dst[0] = sAcc0;
            dst[1] = sAcc1;
        }
        __syncthreads();            // barrier #1: mS/sS complete across warps

        // ---- epilogue: row = tid ----
        const int row = tid;
        float logit = __ldg(b2);
        #pragma unroll
        for (int hh = 0; hh < 16; hh++) {
            const float pre = 64.f * mS[row * MSTR + hh] + __ldg(&b1[hh]) - sS[hh];
            logit += fmaxf(pre, 0.f) * __ldg(&W2[hh]);
        }

        float mx = logit;
        #pragma unroll
        for (int o = 16; o >= 1; o >>= 1)
            mx = fmaxf(mx, __shfl_xor_sync(0xffffffffu, mx, o));
        if (lane == 0) red[0][p] = mx;
        __syncthreads();            // barrier #2
        const float mxAll = fmaxf(red[0][0], red[0][1]);

        const float e = __expf(logit - mxAll);
        float sm = e;
        #pragma unroll
        for (int o = 16; o >= 1; o >>= 1)
            sm += __shfl_xor_sync(0xffffffffu, sm, o);
        if (lane == 0) red[1][p] = sm;
        __syncthreads();            // barrier #3 (also guards mS reuse next batch)
        const float inv = 1.0f / (red[1][0] + red[1][1]);

        out[(size_t)b * Nn + row] = e * inv;
    }
}

extern "C" void kernel_launch(void* const* d_in, const int* in_sizes, int n_in,
                              void* d_out, int out_size)
{
    attn_kernel<<<Bb / 2, THREADS>>>(
        (const float*)d_in[0],   // members_embeds [2048,64,256]
        (const float*)d_in[1],   // item_embeds    [2048,256]
        (const float*)d_in[2],   // W1 [256,16]
        (const float*)d_in[3],   // b1 [16]
        (const float*)d_in[4],   // W2 [16,1]
        (const float*)d_in[5],   // b2 [1]
        (float*)d_out);          // out [2048,64]
}